// round 14
// baseline (speedup 1.0000x reference)
#include <cuda_runtime.h>
#include <cuda_fp16.h>
#include <math.h>
#include <stdint.h>

// Problem constants
#define BATCH   32
#define SEQ     512
#define DIM     1024
#define FFN     2048
#define GDOM    4
#define NTOK    (BATCH * SEQ)
#define LN_EPS  1e-6f

// GEMM tiling: 128x128 CTA, BK=64 halves, 256 threads (8 warps, 2m x 4n)
#define BM 128
#define BN 128
#define BKK 64
#define NSTG 3
#define PADH 72                               // halves per k-row (64 data + 8 pad)
#define STAGE_H ((BM + BN) * PADH)            // 18432 halves = 36864 B per stage
#define SMEM_BYTES (NSTG * STAGE_H * 2)       // 110592

// ---------------------------------------------------------------------------
// Scratch (device globals; allocation-free per harness rules)
// ---------------------------------------------------------------------------
__device__ __half g_ln [(size_t)NTOK * DIM];        // 32 MB LN output (fp16)
__device__ __half g_h  [(size_t)NTOK * FFN];        // 64 MB hidden (fp16)
__device__ __half g_w1t[(size_t)GDOM * FFN * DIM];  // 16 MB W1^T [g][F][D]
__device__ __half g_w2t[(size_t)GDOM * DIM * FFN];  // 16 MB W2^T [g][D][F]

// ---------------------------------------------------------------------------
// PTX helpers
// ---------------------------------------------------------------------------
__device__ __forceinline__ uint32_t smem_u32(const void* p) {
    uint32_t a;
    asm("{ .reg .u64 t; cvta.to.shared.u64 t, %1; cvt.u32.u64 %0, t; }"
        : "=r"(a) : "l"(p));
    return a;
}
__device__ __forceinline__ void cp_async16(void* s, const void* g) {
    uint32_t sa = smem_u32(s);
    asm volatile("cp.async.cg.shared.global [%0], [%1], 16;" :: "r"(sa), "l"(g));
}
#define CP_COMMIT() asm volatile("cp.async.commit_group;" ::: "memory")
#define CP_WAIT(n)  asm volatile("cp.async.wait_group %0;" :: "n"(n) : "memory")

__device__ __forceinline__ void ldsm_x4(uint32_t& r0, uint32_t& r1,
                                        uint32_t& r2, uint32_t& r3,
                                        uint32_t addr) {
    asm volatile("ldmatrix.sync.aligned.m8n8.x4.shared.b16 {%0,%1,%2,%3}, [%4];"
                 : "=r"(r0), "=r"(r1), "=r"(r2), "=r"(r3) : "r"(addr));
}

__device__ __forceinline__ void mma_f16(float* c, const uint32_t* a,
                                        const uint32_t* b) {
    asm volatile(
        "mma.sync.aligned.m16n8k16.row.col.f32.f16.f16.f32 "
        "{%0,%1,%2,%3}, {%4,%5,%6,%7}, {%8,%9}, {%0,%1,%2,%3};"
        : "+f"(c[0]), "+f"(c[1]), "+f"(c[2]), "+f"(c[3])
        : "r"(a[0]), "r"(a[1]), "r"(a[2]), "r"(a[3]), "r"(b[0]), "r"(b[1]));
}

// streaming (evict-first) load/store for use-once data
__device__ __forceinline__ float2 ldcs_f2(const float* p) {
    float2 v;
    asm volatile("ld.global.cs.v2.f32 {%0,%1}, [%2];"
                 : "=f"(v.x), "=f"(v.y) : "l"(p));
    return v;
}
__device__ __forceinline__ void stcs_f2(float* p, float2 v) {
    asm volatile("st.global.cs.v2.f32 [%0], {%1,%2};"
                 :: "l"(p), "f"(v.x), "f"(v.y) : "memory");
}
__device__ __forceinline__ void stcs_u32(uint32_t* p, uint32_t v) {
    asm volatile("st.global.cs.b32 [%0], %1;" :: "l"(p), "r"(v) : "memory");
}

// inline batch -> domain lookup (idx is a disjoint 4x8 partition of 0..31)
__device__ __forceinline__ int dom_of(const int* __restrict__ idx, int batch) {
    int g = 0;
    #pragma unroll
    for (int i = 0; i < BATCH; i++)
        if (__ldg(idx + i) == batch) g = i >> 3;
    return g;
}

// ---------------------------------------------------------------------------
// K1 (fused prep): W1 transpose | W2 transpose | LayerNorm, role by blockIdx.
// Transpose: 64x64 tiles, float4 loads, uint4 (8xhalf) stores.
// ---------------------------------------------------------------------------
#define T_W1   (GDOM * (DIM / 64) * (FFN / 64))    // 2048
#define T_W2   (GDOM * (FFN / 64) * (DIM / 64))    // 2048
#define PREP_GRID (T_W1 + T_W2 + NTOK)             // 20480

__global__ __launch_bounds__(256)
void prep_kernel(const float* __restrict__ W1, const float* __restrict__ W2,
                 const float* __restrict__ x, const float* __restrict__ G,
                 const float* __restrict__ Bn, const int* __restrict__ idx) {
    __shared__ float tb[64][65];
    __shared__ float red_s[8], red_ss[8];
    __shared__ float s_mu, s_inv;

    const int bid = blockIdx.x;
    const int tid = threadIdx.x;

    if (bid < T_W1 + T_W2) {
        // ---- weight transpose role: W[g][R][C] fp32 -> Wt[g][C][R] fp16 ----
        const bool isw1 = bid < T_W1;
        const int id  = isw1 ? bid : bid - T_W1;
        const int R   = isw1 ? DIM : FFN;
        const int C   = isw1 ? FFN : DIM;
        const int ctiles = C / 64;
        const int g   = id / ((R / 64) * ctiles);
        const int rem = id % ((R / 64) * ctiles);
        const int cy  = rem / ctiles;
        const int cx  = rem % ctiles;
        const float* Wg  = (isw1 ? W1 : W2) + (size_t)g * R * C;
        __half*      Wtg = (isw1 ? g_w1t : g_w2t) + (size_t)g * R * C;
        const int r0 = cy * 64, c0 = cx * 64;

        #pragma unroll
        for (int i = 0; i < 4; i++) {
            int idx2 = tid + i * 256;
            int fr  = idx2 >> 4;
            int fc4 = idx2 & 15;
            float4 v = *(const float4*)(Wg + (size_t)(r0 + fr) * C + c0 + fc4 * 4);
            tb[fr][fc4 * 4 + 0] = v.x;
            tb[fr][fc4 * 4 + 1] = v.y;
            tb[fr][fc4 * 4 + 2] = v.z;
            tb[fr][fc4 * 4 + 3] = v.w;
        }
        __syncthreads();

        #pragma unroll
        for (int i = 0; i < 2; i++) {
            int idx2 = tid + i * 256;
            int oc = idx2 >> 3;
            int og = idx2 & 7;
            __half hv[8];
            #pragma unroll
            for (int j = 0; j < 8; j++)
                hv[j] = __float2half_rn(tb[og * 8 + j][oc]);
            *(uint4*)(Wtg + (size_t)(c0 + oc) * R + r0 + og * 8) =
                *(const uint4*)hv;
        }
        return;
    }

    // ---- layernorm role ----
    const int r = bid - (T_W1 + T_W2);
    const int g = dom_of(idx, r >> 9);

    const float4 v = ((const float4*)(x + (size_t)r * DIM))[tid];
    float s  = v.x + v.y + v.z + v.w;
    float ss = v.x * v.x + v.y * v.y + v.z * v.z + v.w * v.w;
    #pragma unroll
    for (int o = 16; o > 0; o >>= 1) {
        s  += __shfl_down_sync(0xffffffffu, s,  o);
        ss += __shfl_down_sync(0xffffffffu, ss, o);
    }
    if ((tid & 31) == 0) { red_s[tid >> 5] = s; red_ss[tid >> 5] = ss; }
    __syncthreads();
    if (tid == 0) {
        float ts = 0.f, tss = 0.f;
        #pragma unroll
        for (int i = 0; i < 8; i++) { ts += red_s[i]; tss += red_ss[i]; }
        float mu  = ts * (1.0f / DIM);
        float var = (tss - (float)DIM * mu * mu) * (1.0f / (DIM - 1));
        var = fmaxf(var, 0.0f);
        s_mu  = mu;
        s_inv = 1.0f / (sqrtf(var) + LN_EPS);
    }
    __syncthreads();
    const float mu = s_mu, inv = s_inv;
    const float4 gv = ((const float4*)(G  + (size_t)g * DIM))[tid];
    const float4 bv = ((const float4*)(Bn + (size_t)g * DIM))[tid];
    float2 y0, y1;
    y0.x = gv.x * (v.x - mu) * inv + bv.x;
    y0.y = gv.y * (v.y - mu) * inv + bv.y;
    y1.x = gv.z * (v.z - mu) * inv + bv.z;
    y1.y = gv.w * (v.w - mu) * inv + bv.w;
    __half2* dst = (__half2*)(g_ln + (size_t)r * DIM);
    dst[tid * 2 + 0] = __float22half2_rn(y0);
    dst[tid * 2 + 1] = __float22half2_rn(y1);
}

// ---------------------------------------------------------------------------
// K2/K3: fp16 mma.sync grouped GEMM, 128x128 tile, 256 threads, BK=64.
// Mainloop identical to round-13 best. Epilogue uses streaming loads/stores
// for use-once data (resid, out) to keep h/W2t resident in L2.
// ---------------------------------------------------------------------------
template<bool RELU, bool RESID, bool OUT_HALF>
__global__ __launch_bounds__(256, 2)
void mma_gemm(const __half* __restrict__ A, const __half* __restrict__ Bt,
              const float* __restrict__ bias, const float* __restrict__ resid,
              void* __restrict__ Cv, const int* __restrict__ idx,
              int N, int K) {
    extern __shared__ __half sm[];
    const int tid  = threadIdx.x;
    const int row0 = blockIdx.y * BM;
    const int col0 = blockIdx.x * BN;
    const int g    = dom_of(idx, row0 >> 9);
    const __half* Bg = Bt + (size_t)g * N * K;

    const int lane  = tid & 31;
    const int wid   = tid >> 5;
    const int gid   = lane >> 2;
    const int tg    = lane & 3;
    const int warpm = wid & 1;        // m offset *64
    const int warpn = wid >> 1;       // n offset *32

    const uint32_t sm_base = smem_u32(sm);

    const uint32_t aoff_b =
        (uint32_t)((warpm * 64 + (lane & 7) + ((lane >> 3) & 1) * 8) * PADH
                   + (lane >> 4) * 8) * 2u;
    const uint32_t boff_b =
        (uint32_t)(BM * PADH) * 2u +
        (uint32_t)((warpn * 32 + (lane & 7) + (lane >> 4) * 8) * PADH
                   + ((lane >> 3) & 1) * 8) * 2u;

    auto load_stage = [&](int kt, int s) {
        const int k0 = kt * BKK;
        __half* As = sm + s * STAGE_H;
        __half* Bs = As + BM * PADH;
        #pragma unroll
        for (int j = 0; j < 4; j++) {
            int c = tid + j * 256;
            int m = c >> 3, kc = (c & 7) << 3;
            cp_async16(&As[m * PADH + kc],
                       A + (size_t)(row0 + m) * K + k0 + kc);
        }
        #pragma unroll
        for (int j = 0; j < 4; j++) {
            int c = tid + j * 256;
            int n = c >> 3, kc = (c & 7) << 3;
            cp_async16(&Bs[n * PADH + kc],
                       Bg + (size_t)(col0 + n) * K + k0 + kc);
        }
        CP_COMMIT();
    };

    auto frag_load = [&](uint32_t base, int ks, uint32_t a[4][4],
                         uint32_t b[4][2]) {
        const uint32_t Aaddr = base + aoff_b + (uint32_t)ks * 32u;
        const uint32_t Baddr = base + boff_b + (uint32_t)ks * 32u;
        #pragma unroll
        for (int mf = 0; mf < 4; mf++)
            ldsm_x4(a[mf][0], a[mf][1], a[mf][2], a[mf][3],
                    Aaddr + (uint32_t)(mf * 16 * PADH) * 2u);
        ldsm_x4(b[0][0], b[0][1], b[1][0], b[1][1], Baddr);
        ldsm_x4(b[2][0], b[2][1], b[3][0], b[3][1],
                Baddr + (uint32_t)(16 * PADH) * 2u);
    };

    float acc[4][4][4];
    #pragma unroll
    for (int i = 0; i < 4; i++)
        #pragma unroll
        for (int j = 0; j < 4; j++)
            #pragma unroll
            for (int q = 0; q < 4; q++) acc[i][j][q] = 0.f;

    const int KT = K / BKK;

    load_stage(0, 0);
    load_stage(1, 1);
    CP_WAIT(1);
    __syncthreads();

    uint32_t a[2][4][4], b[2][4][2];
    int s_cur = 0;
    int s_ld  = NSTG - 1;
    frag_load(sm_base, 0, a[0], b[0]);

    for (int kt = 0; kt < KT; kt++) {
        {
            int nx = kt + NSTG - 1;
            if (nx < KT) load_stage(nx, s_ld);
            else CP_COMMIT();
            if (++s_ld == NSTG) s_ld = 0;
        }
        const uint32_t base_cur = sm_base + (uint32_t)(s_cur * STAGE_H) * 2u;
        const int s_nxt = (s_cur + 1 == NSTG) ? 0 : s_cur + 1;
        const uint32_t base_nxt = sm_base + (uint32_t)(s_nxt * STAGE_H) * 2u;
        s_cur = s_nxt;

        #pragma unroll
        for (int ks = 0; ks < 3; ks++) {
            const int cb = ks & 1, nb = cb ^ 1;
            frag_load(base_cur, ks + 1, a[nb], b[nb]);
            #pragma unroll
            for (int mf = 0; mf < 4; mf++)
                #pragma unroll
                for (int nf = 0; nf < 4; nf++)
                    mma_f16(acc[mf][nf], a[cb][mf], b[cb][nf]);
        }

        if (kt + 1 < KT) {
            CP_WAIT(1);
            __syncthreads();
            frag_load(base_nxt, 0, a[0], b[0]);
        }

        #pragma unroll
        for (int mf = 0; mf < 4; mf++)
            #pragma unroll
            for (int nf = 0; nf < 4; nf++)
                mma_f16(acc[mf][nf], a[1][mf], b[1][nf]);
    }

    // epilogue: bias via float2; resid/out streamed (use-once)
    const float* biasg = bias + (size_t)g * N;
    #pragma unroll
    for (int mf = 0; mf < 4; mf++) {
        #pragma unroll
        for (int h = 0; h < 2; h++) {
            const int r = row0 + warpm * 64 + mf * 16 + gid + h * 8;
            const float* rrow = RESID ? (resid + (size_t)r * N) : nullptr;
            #pragma unroll
            for (int nf = 0; nf < 4; nf++) {
                const int cidx = col0 + warpn * 32 + nf * 8 + tg * 2;
                const float2 bb = *(const float2*)(biasg + cidx);
                float2 v;
                v.x = acc[mf][nf][h * 2 + 0] + bb.x;
                v.y = acc[mf][nf][h * 2 + 1] + bb.y;
                if (RELU) { v.x = fmaxf(v.x, 0.f); v.y = fmaxf(v.y, 0.f); }
                if (RESID) {
                    const float2 xv = ldcs_f2(rrow + cidx);
                    v.x += xv.x; v.y += xv.y;
                }
                if (OUT_HALF) {
                    __half2 hv = __float22half2_rn(v);
                    stcs_u32((uint32_t*)((__half*)Cv + (size_t)r * N + cidx),
                             *(const uint32_t*)&hv);
                } else {
                    stcs_f2((float*)Cv + (size_t)r * N + cidx, v);
                }
            }
        }
    }
}

// ---------------------------------------------------------------------------
extern "C" void kernel_launch(void* const* d_in, const int* in_sizes, int n_in,
                              void* d_out, int out_size) {
    const float* x   = (const float*)d_in[0];
    const int*   idx = (const int*)  d_in[1];
    const float* W1  = (const float*)d_in[2];
    const float* B1  = (const float*)d_in[3];
    const float* W2  = (const float*)d_in[4];
    const float* B2  = (const float*)d_in[5];
    const float* G   = (const float*)d_in[6];
    const float* Bn  = (const float*)d_in[7];
    float*       out = (float*)d_out;

    __half *ln_ptr, *h_ptr, *w1t_ptr, *w2t_ptr;
    cudaGetSymbolAddress((void**)&ln_ptr,  g_ln);
    cudaGetSymbolAddress((void**)&h_ptr,   g_h);
    cudaGetSymbolAddress((void**)&w1t_ptr, g_w1t);
    cudaGetSymbolAddress((void**)&w2t_ptr, g_w2t);

    static bool attr_done = false;
    if (!attr_done) {
        cudaFuncSetAttribute(mma_gemm<true, false, true>,
                             cudaFuncAttributeMaxDynamicSharedMemorySize, SMEM_BYTES);
        cudaFuncSetAttribute(mma_gemm<false, true, false>,
                             cudaFuncAttributeMaxDynamicSharedMemorySize, SMEM_BYTES);
        attr_done = true;
    }

    // fused: W1^T, W2^T, layernorm (domain looked up inline from idx)
    prep_kernel<<<PREP_GRID, 256>>>(W1, W2, x, G, Bn, idx);

    // gemm1: h = relu(ln @ W1[g] + B1[g]) -> fp16   (KT = 16)
    mma_gemm<true, false, true><<<dim3(FFN / BN, NTOK / BM), 256, SMEM_BYTES>>>(
        ln_ptr, w1t_ptr, B1, nullptr, h_ptr, idx, FFN, DIM);

    // gemm2: out = x + h @ W2[g] + B2[g] -> fp32    (KT = 32)
    mma_gemm<false, true, false><<<dim3(DIM / BN, NTOK / BM), 256, SMEM_BYTES>>>(
        h_ptr, w2t_ptr, B2, x, out, idx, DIM, FFN);
}

// round 15
// speedup vs baseline: 1.0644x; 1.0644x over previous
#include <cuda_runtime.h>
#include <cuda_fp16.h>
#include <math.h>
#include <stdint.h>

// Problem constants
#define BATCH   32
#define SEQ     512
#define DIM     1024
#define FFN     2048
#define GDOM    4
#define NTOK    (BATCH * SEQ)
#define LN_EPS  1e-6f

// GEMM tiling: 128x128 CTA, BK=64 halves, 256 threads (8 warps, 2m x 4n)
#define BM 128
#define BN 128
#define BKK 64
#define NSTG 3
#define PADH 72                               // halves per k-row (64 data + 8 pad)
#define STAGE_H ((BM + BN) * PADH)            // 18432 halves = 36864 B per stage
#define SMEM_BYTES (NSTG * STAGE_H * 2)       // 110592

// ---------------------------------------------------------------------------
// Scratch (device globals; allocation-free per harness rules)
// ---------------------------------------------------------------------------
__device__ __half g_ln [(size_t)NTOK * DIM];        // 32 MB LN output (fp16)
__device__ __half g_h  [(size_t)NTOK * FFN];        // 64 MB hidden (fp16)
__device__ __half g_w1t[(size_t)GDOM * FFN * DIM];  // 16 MB W1^T [g][F][D]
__device__ __half g_w2t[(size_t)GDOM * DIM * FFN];  // 16 MB W2^T [g][D][F]
__device__ int    g_dom[BATCH];

// ---------------------------------------------------------------------------
// PTX helpers
// ---------------------------------------------------------------------------
__device__ __forceinline__ uint32_t smem_u32(const void* p) {
    uint32_t a;
    asm("{ .reg .u64 t; cvta.to.shared.u64 t, %1; cvt.u32.u64 %0, t; }"
        : "=r"(a) : "l"(p));
    return a;
}
__device__ __forceinline__ void cp_async16(void* s, const void* g) {
    uint32_t sa = smem_u32(s);
    asm volatile("cp.async.cg.shared.global [%0], [%1], 16;" :: "r"(sa), "l"(g));
}
#define CP_COMMIT() asm volatile("cp.async.commit_group;" ::: "memory")
#define CP_WAIT(n)  asm volatile("cp.async.wait_group %0;" :: "n"(n) : "memory")

__device__ __forceinline__ void ldsm_x4(uint32_t& r0, uint32_t& r1,
                                        uint32_t& r2, uint32_t& r3,
                                        uint32_t addr) {
    asm volatile("ldmatrix.sync.aligned.m8n8.x4.shared.b16 {%0,%1,%2,%3}, [%4];"
                 : "=r"(r0), "=r"(r1), "=r"(r2), "=r"(r3) : "r"(addr));
}

__device__ __forceinline__ void mma_f16(float* c, const uint32_t* a,
                                        const uint32_t* b) {
    asm volatile(
        "mma.sync.aligned.m16n8k16.row.col.f32.f16.f16.f32 "
        "{%0,%1,%2,%3}, {%4,%5,%6,%7}, {%8,%9}, {%0,%1,%2,%3};"
        : "+f"(c[0]), "+f"(c[1]), "+f"(c[2]), "+f"(c[3])
        : "r"(a[0]), "r"(a[1]), "r"(a[2]), "r"(a[3]), "r"(b[0]), "r"(b[1]));
}

// ---------------------------------------------------------------------------
// K0: batch -> domain
// ---------------------------------------------------------------------------
__global__ void dom_kernel(const int* __restrict__ idx) {
    int i = threadIdx.x;
    if (i < BATCH) g_dom[idx[i]] = i >> 3;
}

// ---------------------------------------------------------------------------
// 64x64 transpose tile: W[g][R][C] fp32 -> Wt[g][C][R] fp16
// ---------------------------------------------------------------------------
__device__ __forceinline__ void transpose_tile(
    const float* __restrict__ W, __half* __restrict__ Wt,
    int R, int C, int id, int tid, float (*tb)[65]) {
    const int ctiles = C / 64;
    const int g   = id / ((R / 64) * ctiles);
    const int rem = id % ((R / 64) * ctiles);
    const int cy  = rem / ctiles;
    const int cx  = rem % ctiles;
    const float* Wg  = W  + (size_t)g * R * C;
    __half*      Wtg = Wt + (size_t)g * R * C;
    const int r0 = cy * 64, c0 = cx * 64;

    #pragma unroll
    for (int i = 0; i < 4; i++) {
        int idx2 = tid + i * 256;
        int fr  = idx2 >> 4;
        int fc4 = idx2 & 15;
        float4 v = *(const float4*)(Wg + (size_t)(r0 + fr) * C + c0 + fc4 * 4);
        tb[fr][fc4 * 4 + 0] = v.x;
        tb[fr][fc4 * 4 + 1] = v.y;
        tb[fr][fc4 * 4 + 2] = v.z;
        tb[fr][fc4 * 4 + 3] = v.w;
    }
    __syncthreads();

    #pragma unroll
    for (int i = 0; i < 2; i++) {
        int idx2 = tid + i * 256;
        int oc = idx2 >> 3;
        int og = idx2 & 7;
        __half hv[8];
        #pragma unroll
        for (int j = 0; j < 8; j++)
            hv[j] = __float2half_rn(tb[og * 8 + j][oc]);
        *(uint4*)(Wtg + (size_t)(c0 + oc) * R + r0 + og * 8) =
            *(const uint4*)hv;
    }
}

// ---------------------------------------------------------------------------
// K1a (main stream): W1 transpose | LayerNorm, role by blockIdx.
// ---------------------------------------------------------------------------
#define T_W1   (GDOM * (DIM / 64) * (FFN / 64))    // 2048
#define T_W2   (GDOM * (FFN / 64) * (DIM / 64))    // 2048
#define PREP_MAIN_GRID (T_W1 + NTOK)               // 18432

__global__ __launch_bounds__(256)
void prep_main_kernel(const float* __restrict__ W1, const float* __restrict__ x,
                      const float* __restrict__ G, const float* __restrict__ Bn) {
    __shared__ float tb[64][65];
    __shared__ float red_s[8], red_ss[8];
    __shared__ float s_mu, s_inv;

    const int bid = blockIdx.x;
    const int tid = threadIdx.x;

    if (bid < T_W1) {
        transpose_tile(W1, g_w1t, DIM, FFN, bid, tid, tb);
        return;
    }

    // ---- layernorm role ----
    const int r = bid - T_W1;
    const int g = g_dom[r >> 9];

    const float4 v = ((const float4*)(x + (size_t)r * DIM))[tid];
    float s  = v.x + v.y + v.z + v.w;
    float ss = v.x * v.x + v.y * v.y + v.z * v.z + v.w * v.w;
    #pragma unroll
    for (int o = 16; o > 0; o >>= 1) {
        s  += __shfl_down_sync(0xffffffffu, s,  o);
        ss += __shfl_down_sync(0xffffffffu, ss, o);
    }
    if ((tid & 31) == 0) { red_s[tid >> 5] = s; red_ss[tid >> 5] = ss; }
    __syncthreads();
    if (tid == 0) {
        float ts = 0.f, tss = 0.f;
        #pragma unroll
        for (int i = 0; i < 8; i++) { ts += red_s[i]; tss += red_ss[i]; }
        float mu  = ts * (1.0f / DIM);
        float var = (tss - (float)DIM * mu * mu) * (1.0f / (DIM - 1));
        var = fmaxf(var, 0.0f);
        s_mu  = mu;
        s_inv = 1.0f / (sqrtf(var) + LN_EPS);
    }
    __syncthreads();
    const float mu = s_mu, inv = s_inv;
    const float4 gv = ((const float4*)(G  + (size_t)g * DIM))[tid];
    const float4 bv = ((const float4*)(Bn + (size_t)g * DIM))[tid];
    float2 y0, y1;
    y0.x = gv.x * (v.x - mu) * inv + bv.x;
    y0.y = gv.y * (v.y - mu) * inv + bv.y;
    y1.x = gv.z * (v.z - mu) * inv + bv.z;
    y1.y = gv.w * (v.w - mu) * inv + bv.w;
    __half2* dst = (__half2*)(g_ln + (size_t)r * DIM);
    dst[tid * 2 + 0] = __float22half2_rn(y0);
    dst[tid * 2 + 1] = __float22half2_rn(y1);
}

// ---------------------------------------------------------------------------
// K1b (side stream, overlaps gemm1): W2 transpose only.
// ---------------------------------------------------------------------------
__global__ __launch_bounds__(256)
void prep_w2_kernel(const float* __restrict__ W2) {
    __shared__ float tb[64][65];
    transpose_tile(W2, g_w2t, FFN, DIM, blockIdx.x, threadIdx.x, tb);
}

// ---------------------------------------------------------------------------
// K2/K3: fp16 mma.sync grouped GEMM, 128x128 tile, 256 threads, BK=64.
// (Mainloop + epilogue identical to the round-13 best.)
// ---------------------------------------------------------------------------
template<bool RELU, bool RESID, bool OUT_HALF>
__global__ __launch_bounds__(256, 2)
void mma_gemm(const __half* __restrict__ A, const __half* __restrict__ Bt,
              const float* __restrict__ bias, const float* __restrict__ resid,
              void* __restrict__ Cv, int N, int K) {
    extern __shared__ __half sm[];
    const int tid  = threadIdx.x;
    const int row0 = blockIdx.y * BM;
    const int col0 = blockIdx.x * BN;
    const int g    = g_dom[row0 >> 9];
    const __half* Bg = Bt + (size_t)g * N * K;

    const int lane  = tid & 31;
    const int wid   = tid >> 5;
    const int gid   = lane >> 2;
    const int tg    = lane & 3;
    const int warpm = wid & 1;
    const int warpn = wid >> 1;

    const uint32_t sm_base = smem_u32(sm);

    const uint32_t aoff_b =
        (uint32_t)((warpm * 64 + (lane & 7) + ((lane >> 3) & 1) * 8) * PADH
                   + (lane >> 4) * 8) * 2u;
    const uint32_t boff_b =
        (uint32_t)(BM * PADH) * 2u +
        (uint32_t)((warpn * 32 + (lane & 7) + (lane >> 4) * 8) * PADH
                   + ((lane >> 3) & 1) * 8) * 2u;

    auto load_stage = [&](int kt, int s) {
        const int k0 = kt * BKK;
        __half* As = sm + s * STAGE_H;
        __half* Bs = As + BM * PADH;
        #pragma unroll
        for (int j = 0; j < 4; j++) {
            int c = tid + j * 256;
            int m = c >> 3, kc = (c & 7) << 3;
            cp_async16(&As[m * PADH + kc],
                       A + (size_t)(row0 + m) * K + k0 + kc);
        }
        #pragma unroll
        for (int j = 0; j < 4; j++) {
            int c = tid + j * 256;
            int n = c >> 3, kc = (c & 7) << 3;
            cp_async16(&Bs[n * PADH + kc],
                       Bg + (size_t)(col0 + n) * K + k0 + kc);
        }
        CP_COMMIT();
    };

    auto frag_load = [&](uint32_t base, int ks, uint32_t a[4][4],
                         uint32_t b[4][2]) {
        const uint32_t Aaddr = base + aoff_b + (uint32_t)ks * 32u;
        const uint32_t Baddr = base + boff_b + (uint32_t)ks * 32u;
        #pragma unroll
        for (int mf = 0; mf < 4; mf++)
            ldsm_x4(a[mf][0], a[mf][1], a[mf][2], a[mf][3],
                    Aaddr + (uint32_t)(mf * 16 * PADH) * 2u);
        ldsm_x4(b[0][0], b[0][1], b[1][0], b[1][1], Baddr);
        ldsm_x4(b[2][0], b[2][1], b[3][0], b[3][1],
                Baddr + (uint32_t)(16 * PADH) * 2u);
    };

    float acc[4][4][4];
    #pragma unroll
    for (int i = 0; i < 4; i++)
        #pragma unroll
        for (int j = 0; j < 4; j++)
            #pragma unroll
            for (int q = 0; q < 4; q++) acc[i][j][q] = 0.f;

    const int KT = K / BKK;

    load_stage(0, 0);
    load_stage(1, 1);
    CP_WAIT(1);
    __syncthreads();

    uint32_t a[2][4][4], b[2][4][2];
    int s_cur = 0;
    int s_ld  = NSTG - 1;
    frag_load(sm_base, 0, a[0], b[0]);

    for (int kt = 0; kt < KT; kt++) {
        {
            int nx = kt + NSTG - 1;
            if (nx < KT) load_stage(nx, s_ld);
            else CP_COMMIT();
            if (++s_ld == NSTG) s_ld = 0;
        }
        const uint32_t base_cur = sm_base + (uint32_t)(s_cur * STAGE_H) * 2u;
        const int s_nxt = (s_cur + 1 == NSTG) ? 0 : s_cur + 1;
        const uint32_t base_nxt = sm_base + (uint32_t)(s_nxt * STAGE_H) * 2u;
        s_cur = s_nxt;

        #pragma unroll
        for (int ks = 0; ks < 3; ks++) {
            const int cb = ks & 1, nb = cb ^ 1;
            frag_load(base_cur, ks + 1, a[nb], b[nb]);
            #pragma unroll
            for (int mf = 0; mf < 4; mf++)
                #pragma unroll
                for (int nf = 0; nf < 4; nf++)
                    mma_f16(acc[mf][nf], a[cb][mf], b[cb][nf]);
        }

        if (kt + 1 < KT) {
            CP_WAIT(1);
            __syncthreads();
            frag_load(base_nxt, 0, a[0], b[0]);
        }

        #pragma unroll
        for (int mf = 0; mf < 4; mf++)
            #pragma unroll
            for (int nf = 0; nf < 4; nf++)
                mma_f16(acc[mf][nf], a[1][mf], b[1][nf]);
    }

    // epilogue (bias via float2)
    const float* biasg = bias + (size_t)g * N;
    #pragma unroll
    for (int mf = 0; mf < 4; mf++) {
        #pragma unroll
        for (int h = 0; h < 2; h++) {
            const int r = row0 + warpm * 64 + mf * 16 + gid + h * 8;
            const float* rrow = RESID ? (resid + (size_t)r * N) : nullptr;
            #pragma unroll
            for (int nf = 0; nf < 4; nf++) {
                const int cidx = col0 + warpn * 32 + nf * 8 + tg * 2;
                const float2 bb = *(const float2*)(biasg + cidx);
                float2 v;
                v.x = acc[mf][nf][h * 2 + 0] + bb.x;
                v.y = acc[mf][nf][h * 2 + 1] + bb.y;
                if (RELU) { v.x = fmaxf(v.x, 0.f); v.y = fmaxf(v.y, 0.f); }
                if (RESID) {
                    const float2 xv = *(const float2*)(rrow + cidx);
                    v.x += xv.x; v.y += xv.y;
                }
                if (OUT_HALF) {
                    __half2* crow = (__half2*)((__half*)Cv + (size_t)r * N + cidx);
                    *crow = __float22half2_rn(v);
                } else {
                    *(float2*)((float*)Cv + (size_t)r * N + cidx) = v;
                }
            }
        }
    }
}

// ---------------------------------------------------------------------------
extern "C" void kernel_launch(void* const* d_in, const int* in_sizes, int n_in,
                              void* d_out, int out_size) {
    const float* x   = (const float*)d_in[0];
    const int*   idx = (const int*)  d_in[1];
    const float* W1  = (const float*)d_in[2];
    const float* B1  = (const float*)d_in[3];
    const float* W2  = (const float*)d_in[4];
    const float* B2  = (const float*)d_in[5];
    const float* G   = (const float*)d_in[6];
    const float* Bn  = (const float*)d_in[7];
    float*       out = (float*)d_out;

    __half *ln_ptr, *h_ptr, *w1t_ptr, *w2t_ptr;
    cudaGetSymbolAddress((void**)&ln_ptr,  g_ln);
    cudaGetSymbolAddress((void**)&h_ptr,   g_h);
    cudaGetSymbolAddress((void**)&w1t_ptr, g_w1t);
    cudaGetSymbolAddress((void**)&w2t_ptr, g_w2t);

    // one-time setup (first call is the uncaptured correctness run)
    static cudaStream_t s_side = nullptr;
    static cudaEvent_t  ev_fork = nullptr, ev_join = nullptr;
    static bool setup_done = false;
    if (!setup_done) {
        cudaFuncSetAttribute(mma_gemm<true, false, true>,
                             cudaFuncAttributeMaxDynamicSharedMemorySize, SMEM_BYTES);
        cudaFuncSetAttribute(mma_gemm<false, true, false>,
                             cudaFuncAttributeMaxDynamicSharedMemorySize, SMEM_BYTES);
        cudaStreamCreateWithFlags(&s_side, cudaStreamNonBlocking);
        cudaEventCreateWithFlags(&ev_fork, cudaEventDisableTiming);
        cudaEventCreateWithFlags(&ev_join, cudaEventDisableTiming);
        setup_done = true;
    }

    // main: dom -> fork
    dom_kernel<<<1, 32>>>(idx);
    cudaEventRecord(ev_fork, 0);

    // side branch: W2 transpose (only needed by gemm2) overlaps gemm1
    cudaStreamWaitEvent(s_side, ev_fork, 0);
    prep_w2_kernel<<<T_W2, 256, 0, s_side>>>(W2);
    cudaEventRecord(ev_join, s_side);

    // main branch: W1 transpose + LN, then gemm1
    prep_main_kernel<<<PREP_MAIN_GRID, 256>>>(W1, x, G, Bn);
    mma_gemm<true, false, true><<<dim3(FFN / BN, NTOK / BM), 256, SMEM_BYTES>>>(
        ln_ptr, w1t_ptr, B1, nullptr, h_ptr, FFN, DIM);

    // join, then gemm2
    cudaStreamWaitEvent(0, ev_join, 0);
    mma_gemm<false, true, false><<<dim3(DIM / BN, NTOK / BM), 256, SMEM_BYTES>>>(
        h_ptr, w2t_ptr, B2, x, out, DIM, FFN);
}

// round 16
// speedup vs baseline: 1.0750x; 1.0100x over previous
#include <cuda_runtime.h>
#include <cuda_fp16.h>
#include <math.h>
#include <stdint.h>

// Problem constants
#define BATCH   32
#define SEQ     512
#define DIM     1024
#define FFN     2048
#define GDOM    4
#define NTOK    (BATCH * SEQ)
#define LN_EPS  1e-6f

// GEMM tiling: 128x128 CTA, BK=64 halves, 256 threads (8 warps, 2m x 4n)
#define BM 128
#define BN 128
#define BKK 64
#define NSTG 3
#define PADH 72                               // halves per k-row (64 data + 8 pad)
#define STAGE_H ((BM + BN) * PADH)            // 18432 halves = 36864 B per stage
#define SMEM_BYTES (NSTG * STAGE_H * 2)       // 110592

// ---------------------------------------------------------------------------
// Scratch (device globals; allocation-free per harness rules)
// ---------------------------------------------------------------------------
__device__ __half g_ln [(size_t)NTOK * DIM];        // 32 MB LN output (fp16)
__device__ __half g_h  [(size_t)NTOK * FFN];        // 64 MB hidden (fp16)
__device__ __half g_w1t[(size_t)GDOM * FFN * DIM];  // 16 MB W1^T [g][F][D]
__device__ __half g_w2t[(size_t)GDOM * DIM * FFN];  // 16 MB W2^T [g][D][F]
__device__ int    g_dom[BATCH];

// ---------------------------------------------------------------------------
// PTX helpers
// ---------------------------------------------------------------------------
__device__ __forceinline__ uint32_t smem_u32(const void* p) {
    uint32_t a;
    asm("{ .reg .u64 t; cvta.to.shared.u64 t, %1; cvt.u32.u64 %0, t; }"
        : "=r"(a) : "l"(p));
    return a;
}
__device__ __forceinline__ void cp_async16(void* s, const void* g) {
    uint32_t sa = smem_u32(s);
    asm volatile("cp.async.cg.shared.global [%0], [%1], 16;" :: "r"(sa), "l"(g));
}
#define CP_COMMIT() asm volatile("cp.async.commit_group;" ::: "memory")
#define CP_WAIT(n)  asm volatile("cp.async.wait_group %0;" :: "n"(n) : "memory")

__device__ __forceinline__ void ldsm_x4(uint32_t& r0, uint32_t& r1,
                                        uint32_t& r2, uint32_t& r3,
                                        uint32_t addr) {
    asm volatile("ldmatrix.sync.aligned.m8n8.x4.shared.b16 {%0,%1,%2,%3}, [%4];"
                 : "=r"(r0), "=r"(r1), "=r"(r2), "=r"(r3) : "r"(addr));
}

__device__ __forceinline__ void mma_f16(float* c, const uint32_t* a,
                                        const uint32_t* b) {
    asm volatile(
        "mma.sync.aligned.m16n8k16.row.col.f32.f16.f16.f32 "
        "{%0,%1,%2,%3}, {%4,%5,%6,%7}, {%8,%9}, {%0,%1,%2,%3};"
        : "+f"(c[0]), "+f"(c[1]), "+f"(c[2]), "+f"(c[3])
        : "r"(a[0]), "r"(a[1]), "r"(a[2]), "r"(a[3]), "r"(b[0]), "r"(b[1]));
}

// ---------------------------------------------------------------------------
// K0: batch -> domain
// ---------------------------------------------------------------------------
__global__ void dom_kernel(const int* __restrict__ idx) {
    int i = threadIdx.x;
    if (i < BATCH) g_dom[idx[i]] = i >> 3;
}

// ---------------------------------------------------------------------------
// 64x64 transpose tile: W[g][R][C] fp32 -> Wt[g][C][R] fp16
// ---------------------------------------------------------------------------
__device__ __forceinline__ void transpose_tile(
    const float* __restrict__ W, __half* __restrict__ Wt,
    int R, int C, int id, int tid, float (*tb)[65]) {
    const int ctiles = C / 64;
    const int g   = id / ((R / 64) * ctiles);
    const int rem = id % ((R / 64) * ctiles);
    const int cy  = rem / ctiles;
    const int cx  = rem % ctiles;
    const float* Wg  = W  + (size_t)g * R * C;
    __half*      Wtg = Wt + (size_t)g * R * C;
    const int r0 = cy * 64, c0 = cx * 64;

    #pragma unroll
    for (int i = 0; i < 4; i++) {
        int idx2 = tid + i * 256;
        int fr  = idx2 >> 4;
        int fc4 = idx2 & 15;
        float4 v = *(const float4*)(Wg + (size_t)(r0 + fr) * C + c0 + fc4 * 4);
        tb[fr][fc4 * 4 + 0] = v.x;
        tb[fr][fc4 * 4 + 1] = v.y;
        tb[fr][fc4 * 4 + 2] = v.z;
        tb[fr][fc4 * 4 + 3] = v.w;
    }
    __syncthreads();

    #pragma unroll
    for (int i = 0; i < 2; i++) {
        int idx2 = tid + i * 256;
        int oc = idx2 >> 3;
        int og = idx2 & 7;
        __half hv[8];
        #pragma unroll
        for (int j = 0; j < 8; j++)
            hv[j] = __float2half_rn(tb[og * 8 + j][oc]);
        *(uint4*)(Wtg + (size_t)(c0 + oc) * R + r0 + og * 8) =
            *(const uint4*)hv;
    }
}

// ---------------------------------------------------------------------------
// K1a (main stream): W1 transpose | warp-per-row LayerNorm, role by blockIdx.
// LN: 8 rows per 256-thread block; 32 lanes x 8 float4 per row; shfl-only
// reduction (no smem, no block barrier), MLP=8.
// ---------------------------------------------------------------------------
#define T_W1   (GDOM * (DIM / 64) * (FFN / 64))    // 2048
#define T_W2   (GDOM * (FFN / 64) * (DIM / 64))    // 2048
#define LN_BLOCKS (NTOK / 8)                       // 2048
#define PREP_MAIN_GRID (T_W1 + LN_BLOCKS)          // 4096

__global__ __launch_bounds__(256)
void prep_main_kernel(const float* __restrict__ W1, const float* __restrict__ x,
                      const float* __restrict__ G, const float* __restrict__ Bn) {
    __shared__ float tb[64][65];

    const int bid = blockIdx.x;
    const int tid = threadIdx.x;

    if (bid < T_W1) {
        transpose_tile(W1, g_w1t, DIM, FFN, bid, tid, tb);
        return;
    }

    // ---- warp-per-row layernorm ----
    const int wid  = tid >> 5;
    const int lane = tid & 31;
    const int r    = (bid - T_W1) * 8 + wid;
    const int g    = g_dom[r >> 9];

    const float4* xr = (const float4*)(x + (size_t)r * DIM);
    float4 v[8];
    #pragma unroll
    for (int q = 0; q < 8; q++) v[q] = xr[lane + q * 32];

    float s = 0.f, ss = 0.f;
    #pragma unroll
    for (int q = 0; q < 8; q++) {
        s  += v[q].x + v[q].y + v[q].z + v[q].w;
        ss += v[q].x * v[q].x + v[q].y * v[q].y
            + v[q].z * v[q].z + v[q].w * v[q].w;
    }
    #pragma unroll
    for (int o = 16; o > 0; o >>= 1) {
        s  += __shfl_xor_sync(0xffffffffu, s,  o);
        ss += __shfl_xor_sync(0xffffffffu, ss, o);
    }
    const float mu  = s * (1.0f / DIM);
    float var = (ss - (float)DIM * mu * mu) * (1.0f / (DIM - 1));
    var = fmaxf(var, 0.0f);
    const float inv = 1.0f / (sqrtf(var) + LN_EPS);

    const float4* gr = (const float4*)(G  + (size_t)g * DIM);
    const float4* br = (const float4*)(Bn + (size_t)g * DIM);
    uint2* dst = (uint2*)(g_ln + (size_t)r * DIM);
    #pragma unroll
    for (int q = 0; q < 8; q++) {
        const float4 gv = gr[lane + q * 32];
        const float4 bv = br[lane + q * 32];
        float2 y0, y1;
        y0.x = gv.x * (v[q].x - mu) * inv + bv.x;
        y0.y = gv.y * (v[q].y - mu) * inv + bv.y;
        y1.x = gv.z * (v[q].z - mu) * inv + bv.z;
        y1.y = gv.w * (v[q].w - mu) * inv + bv.w;
        __half2 h0 = __float22half2_rn(y0);
        __half2 h1 = __float22half2_rn(y1);
        uint2 o2;
        o2.x = *(const uint32_t*)&h0;
        o2.y = *(const uint32_t*)&h1;
        dst[lane + q * 32] = o2;
    }
}

// ---------------------------------------------------------------------------
// K1b (side stream, overlaps gemm1): W2 transpose only.
// ---------------------------------------------------------------------------
__global__ __launch_bounds__(256)
void prep_w2_kernel(const float* __restrict__ W2) {
    __shared__ float tb[64][65];
    transpose_tile(W2, g_w2t, FFN, DIM, blockIdx.x, threadIdx.x, tb);
}

// ---------------------------------------------------------------------------
// K2/K3: fp16 mma.sync grouped GEMM, 128x128 tile, 256 threads, BK=64.
// (Mainloop + epilogue identical to the round-13/15 best.)
// ---------------------------------------------------------------------------
template<bool RELU, bool RESID, bool OUT_HALF>
__global__ __launch_bounds__(256, 2)
void mma_gemm(const __half* __restrict__ A, const __half* __restrict__ Bt,
              const float* __restrict__ bias, const float* __restrict__ resid,
              void* __restrict__ Cv, int N, int K) {
    extern __shared__ __half sm[];
    const int tid  = threadIdx.x;
    const int row0 = blockIdx.y * BM;
    const int col0 = blockIdx.x * BN;
    const int g    = g_dom[row0 >> 9];
    const __half* Bg = Bt + (size_t)g * N * K;

    const int lane  = tid & 31;
    const int wid   = tid >> 5;
    const int gid   = lane >> 2;
    const int tg    = lane & 3;
    const int warpm = wid & 1;
    const int warpn = wid >> 1;

    const uint32_t sm_base = smem_u32(sm);

    const uint32_t aoff_b =
        (uint32_t)((warpm * 64 + (lane & 7) + ((lane >> 3) & 1) * 8) * PADH
                   + (lane >> 4) * 8) * 2u;
    const uint32_t boff_b =
        (uint32_t)(BM * PADH) * 2u +
        (uint32_t)((warpn * 32 + (lane & 7) + (lane >> 4) * 8) * PADH
                   + ((lane >> 3) & 1) * 8) * 2u;

    auto load_stage = [&](int kt, int s) {
        const int k0 = kt * BKK;
        __half* As = sm + s * STAGE_H;
        __half* Bs = As + BM * PADH;
        #pragma unroll
        for (int j = 0; j < 4; j++) {
            int c = tid + j * 256;
            int m = c >> 3, kc = (c & 7) << 3;
            cp_async16(&As[m * PADH + kc],
                       A + (size_t)(row0 + m) * K + k0 + kc);
        }
        #pragma unroll
        for (int j = 0; j < 4; j++) {
            int c = tid + j * 256;
            int n = c >> 3, kc = (c & 7) << 3;
            cp_async16(&Bs[n * PADH + kc],
                       Bg + (size_t)(col0 + n) * K + k0 + kc);
        }
        CP_COMMIT();
    };

    auto frag_load = [&](uint32_t base, int ks, uint32_t a[4][4],
                         uint32_t b[4][2]) {
        const uint32_t Aaddr = base + aoff_b + (uint32_t)ks * 32u;
        const uint32_t Baddr = base + boff_b + (uint32_t)ks * 32u;
        #pragma unroll
        for (int mf = 0; mf < 4; mf++)
            ldsm_x4(a[mf][0], a[mf][1], a[mf][2], a[mf][3],
                    Aaddr + (uint32_t)(mf * 16 * PADH) * 2u);
        ldsm_x4(b[0][0], b[0][1], b[1][0], b[1][1], Baddr);
        ldsm_x4(b[2][0], b[2][1], b[3][0], b[3][1],
                Baddr + (uint32_t)(16 * PADH) * 2u);
    };

    float acc[4][4][4];
    #pragma unroll
    for (int i = 0; i < 4; i++)
        #pragma unroll
        for (int j = 0; j < 4; j++)
            #pragma unroll
            for (int q = 0; q < 4; q++) acc[i][j][q] = 0.f;

    const int KT = K / BKK;

    load_stage(0, 0);
    load_stage(1, 1);
    CP_WAIT(1);
    __syncthreads();

    uint32_t a[2][4][4], b[2][4][2];
    int s_cur = 0;
    int s_ld  = NSTG - 1;
    frag_load(sm_base, 0, a[0], b[0]);

    for (int kt = 0; kt < KT; kt++) {
        {
            int nx = kt + NSTG - 1;
            if (nx < KT) load_stage(nx, s_ld);
            else CP_COMMIT();
            if (++s_ld == NSTG) s_ld = 0;
        }
        const uint32_t base_cur = sm_base + (uint32_t)(s_cur * STAGE_H) * 2u;
        const int s_nxt = (s_cur + 1 == NSTG) ? 0 : s_cur + 1;
        const uint32_t base_nxt = sm_base + (uint32_t)(s_nxt * STAGE_H) * 2u;
        s_cur = s_nxt;

        #pragma unroll
        for (int ks = 0; ks < 3; ks++) {
            const int cb = ks & 1, nb = cb ^ 1;
            frag_load(base_cur, ks + 1, a[nb], b[nb]);
            #pragma unroll
            for (int mf = 0; mf < 4; mf++)
                #pragma unroll
                for (int nf = 0; nf < 4; nf++)
                    mma_f16(acc[mf][nf], a[cb][mf], b[cb][nf]);
        }

        if (kt + 1 < KT) {
            CP_WAIT(1);
            __syncthreads();
            frag_load(base_nxt, 0, a[0], b[0]);
        }

        #pragma unroll
        for (int mf = 0; mf < 4; mf++)
            #pragma unroll
            for (int nf = 0; nf < 4; nf++)
                mma_f16(acc[mf][nf], a[1][mf], b[1][nf]);
    }

    // epilogue (bias via float2)
    const float* biasg = bias + (size_t)g * N;
    #pragma unroll
    for (int mf = 0; mf < 4; mf++) {
        #pragma unroll
        for (int h = 0; h < 2; h++) {
            const int r = row0 + warpm * 64 + mf * 16 + gid + h * 8;
            const float* rrow = RESID ? (resid + (size_t)r * N) : nullptr;
            #pragma unroll
            for (int nf = 0; nf < 4; nf++) {
                const int cidx = col0 + warpn * 32 + nf * 8 + tg * 2;
                const float2 bb = *(const float2*)(biasg + cidx);
                float2 v;
                v.x = acc[mf][nf][h * 2 + 0] + bb.x;
                v.y = acc[mf][nf][h * 2 + 1] + bb.y;
                if (RELU) { v.x = fmaxf(v.x, 0.f); v.y = fmaxf(v.y, 0.f); }
                if (RESID) {
                    const float2 xv = *(const float2*)(rrow + cidx);
                    v.x += xv.x; v.y += xv.y;
                }
                if (OUT_HALF) {
                    __half2* crow = (__half2*)((__half*)Cv + (size_t)r * N + cidx);
                    *crow = __float22half2_rn(v);
                } else {
                    *(float2*)((float*)Cv + (size_t)r * N + cidx) = v;
                }
            }
        }
    }
}

// ---------------------------------------------------------------------------
extern "C" void kernel_launch(void* const* d_in, const int* in_sizes, int n_in,
                              void* d_out, int out_size) {
    const float* x   = (const float*)d_in[0];
    const int*   idx = (const int*)  d_in[1];
    const float* W1  = (const float*)d_in[2];
    const float* B1  = (const float*)d_in[3];
    const float* W2  = (const float*)d_in[4];
    const float* B2  = (const float*)d_in[5];
    const float* G   = (const float*)d_in[6];
    const float* Bn  = (const float*)d_in[7];
    float*       out = (float*)d_out;

    __half *ln_ptr, *h_ptr, *w1t_ptr, *w2t_ptr;
    cudaGetSymbolAddress((void**)&ln_ptr,  g_ln);
    cudaGetSymbolAddress((void**)&h_ptr,   g_h);
    cudaGetSymbolAddress((void**)&w1t_ptr, g_w1t);
    cudaGetSymbolAddress((void**)&w2t_ptr, g_w2t);

    // one-time setup (first call is the uncaptured correctness run)
    static cudaStream_t s_side = nullptr;
    static cudaEvent_t  ev_fork = nullptr, ev_join = nullptr;
    static bool setup_done = false;
    if (!setup_done) {
        cudaFuncSetAttribute(mma_gemm<true, false, true>,
                             cudaFuncAttributeMaxDynamicSharedMemorySize, SMEM_BYTES);
        cudaFuncSetAttribute(mma_gemm<false, true, false>,
                             cudaFuncAttributeMaxDynamicSharedMemorySize, SMEM_BYTES);
        cudaStreamCreateWithFlags(&s_side, cudaStreamNonBlocking);
        cudaEventCreateWithFlags(&ev_fork, cudaEventDisableTiming);
        cudaEventCreateWithFlags(&ev_join, cudaEventDisableTiming);
        setup_done = true;
    }

    // main: dom -> fork
    dom_kernel<<<1, 32>>>(idx);
    cudaEventRecord(ev_fork, 0);

    // side branch: W2 transpose (only needed by gemm2) overlaps gemm1
    cudaStreamWaitEvent(s_side, ev_fork, 0);
    prep_w2_kernel<<<T_W2, 256, 0, s_side>>>(W2);
    cudaEventRecord(ev_join, s_side);

    // main branch: W1 transpose + warp-per-row LN, then gemm1
    prep_main_kernel<<<PREP_MAIN_GRID, 256>>>(W1, x, G, Bn);
    mma_gemm<true, false, true><<<dim3(FFN / BN, NTOK / BM), 256, SMEM_BYTES>>>(
        ln_ptr, w1t_ptr, B1, nullptr, h_ptr, FFN, DIM);

    // join, then gemm2
    cudaStreamWaitEvent(0, ev_join, 0);
    mma_gemm<false, true, false><<<dim3(DIM / BN, NTOK / BM), 256, SMEM_BYTES>>>(
        h_ptr, w2t_ptr, B2, x, out, DIM, FFN);
}

// round 17
// speedup vs baseline: 1.0848x; 1.0091x over previous
#include <cuda_runtime.h>
#include <cuda_fp16.h>
#include <math.h>
#include <stdint.h>

// Problem constants
#define BATCH   32
#define SEQ     512
#define DIM     1024
#define FFN     2048
#define GDOM    4
#define NTOK    (BATCH * SEQ)
#define LN_EPS  1e-6f

// GEMM tiling: 128x128 CTA, BK=64 halves, 256 threads (8 warps, 2m x 4n)
#define BM 128
#define BN 128
#define BKK 64
#define NSTG 3
#define PADH 72                               // halves per k-row (64 data + 8 pad)
#define STAGE_H ((BM + BN) * PADH)            // 18432 halves = 36864 B per stage
#define SMEM_BYTES (NSTG * STAGE_H * 2)       // 110592

#define HALF_ROWS (NTOK / 2)                  // 8192 (SEQ-aligned)

// ---------------------------------------------------------------------------
// Scratch (device globals; allocation-free per harness rules)
// ---------------------------------------------------------------------------
__device__ __half g_ln [(size_t)NTOK * DIM];        // 32 MB LN output (fp16)
__device__ __half g_h  [(size_t)NTOK * FFN];        // 64 MB hidden (fp16)
__device__ __half g_w1t[(size_t)GDOM * FFN * DIM];  // 16 MB W1^T [g][F][D]
__device__ __half g_w2t[(size_t)GDOM * DIM * FFN];  // 16 MB W2^T [g][D][F]
__device__ int    g_dom[BATCH];

// ---------------------------------------------------------------------------
// PTX helpers
// ---------------------------------------------------------------------------
__device__ __forceinline__ uint32_t smem_u32(const void* p) {
    uint32_t a;
    asm("{ .reg .u64 t; cvta.to.shared.u64 t, %1; cvt.u32.u64 %0, t; }"
        : "=r"(a) : "l"(p));
    return a;
}
__device__ __forceinline__ void cp_async16(void* s, const void* g) {
    uint32_t sa = smem_u32(s);
    asm volatile("cp.async.cg.shared.global [%0], [%1], 16;" :: "r"(sa), "l"(g));
}
#define CP_COMMIT() asm volatile("cp.async.commit_group;" ::: "memory")
#define CP_WAIT(n)  asm volatile("cp.async.wait_group %0;" :: "n"(n) : "memory")

__device__ __forceinline__ void ldsm_x4(uint32_t& r0, uint32_t& r1,
                                        uint32_t& r2, uint32_t& r3,
                                        uint32_t addr) {
    asm volatile("ldmatrix.sync.aligned.m8n8.x4.shared.b16 {%0,%1,%2,%3}, [%4];"
                 : "=r"(r0), "=r"(r1), "=r"(r2), "=r"(r3) : "r"(addr));
}

__device__ __forceinline__ void mma_f16(float* c, const uint32_t* a,
                                        const uint32_t* b) {
    asm volatile(
        "mma.sync.aligned.m16n8k16.row.col.f32.f16.f16.f32 "
        "{%0,%1,%2,%3}, {%4,%5,%6,%7}, {%8,%9}, {%0,%1,%2,%3};"
        : "+f"(c[0]), "+f"(c[1]), "+f"(c[2]), "+f"(c[3])
        : "r"(a[0]), "r"(a[1]), "r"(a[2]), "r"(a[3]), "r"(b[0]), "r"(b[1]));
}

// ---------------------------------------------------------------------------
// K0: batch -> domain
// ---------------------------------------------------------------------------
__global__ void dom_kernel(const int* __restrict__ idx) {
    int i = threadIdx.x;
    if (i < BATCH) g_dom[idx[i]] = i >> 3;
}

// ---------------------------------------------------------------------------
// 64x64 transpose tile: W[g][R][C] fp32 -> Wt[g][C][R] fp16
// ---------------------------------------------------------------------------
__device__ __forceinline__ void transpose_tile(
    const float* __restrict__ W, __half* __restrict__ Wt,
    int R, int C, int id, int tid, float (*tb)[65]) {
    const int ctiles = C / 64;
    const int g   = id / ((R / 64) * ctiles);
    const int rem = id % ((R / 64) * ctiles);
    const int cy  = rem / ctiles;
    const int cx  = rem % ctiles;
    const float* Wg  = W  + (size_t)g * R * C;
    __half*      Wtg = Wt + (size_t)g * R * C;
    const int r0 = cy * 64, c0 = cx * 64;

    #pragma unroll
    for (int i = 0; i < 4; i++) {
        int idx2 = tid + i * 256;
        int fr  = idx2 >> 4;
        int fc4 = idx2 & 15;
        float4 v = *(const float4*)(Wg + (size_t)(r0 + fr) * C + c0 + fc4 * 4);
        tb[fr][fc4 * 4 + 0] = v.x;
        tb[fr][fc4 * 4 + 1] = v.y;
        tb[fr][fc4 * 4 + 2] = v.z;
        tb[fr][fc4 * 4 + 3] = v.w;
    }
    __syncthreads();

    #pragma unroll
    for (int i = 0; i < 2; i++) {
        int idx2 = tid + i * 256;
        int oc = idx2 >> 3;
        int og = idx2 & 7;
        __half hv[8];
        #pragma unroll
        for (int j = 0; j < 8; j++)
            hv[j] = __float2half_rn(tb[og * 8 + j][oc]);
        *(uint4*)(Wtg + (size_t)(c0 + oc) * R + r0 + og * 8) =
            *(const uint4*)hv;
    }
}

// ---------------------------------------------------------------------------
// K1a (main stream): W1 transpose | warp-per-row LayerNorm, role by blockIdx.
// ---------------------------------------------------------------------------
#define T_W1   (GDOM * (DIM / 64) * (FFN / 64))    // 2048
#define T_W2   (GDOM * (FFN / 64) * (DIM / 64))    // 2048
#define LN_BLOCKS (NTOK / 8)                       // 2048
#define PREP_MAIN_GRID (T_W1 + LN_BLOCKS)          // 4096

__global__ __launch_bounds__(256)
void prep_main_kernel(const float* __restrict__ W1, const float* __restrict__ x,
                      const float* __restrict__ G, const float* __restrict__ Bn) {
    __shared__ float tb[64][65];

    const int bid = blockIdx.x;
    const int tid = threadIdx.x;

    if (bid < T_W1) {
        transpose_tile(W1, g_w1t, DIM, FFN, bid, tid, tb);
        return;
    }

    // ---- warp-per-row layernorm ----
    const int wid  = tid >> 5;
    const int lane = tid & 31;
    const int r    = (bid - T_W1) * 8 + wid;
    const int g    = g_dom[r >> 9];

    const float4* xr = (const float4*)(x + (size_t)r * DIM);
    float4 v[8];
    #pragma unroll
    for (int q = 0; q < 8; q++) v[q] = xr[lane + q * 32];

    float s = 0.f, ss = 0.f;
    #pragma unroll
    for (int q = 0; q < 8; q++) {
        s  += v[q].x + v[q].y + v[q].z + v[q].w;
        ss += v[q].x * v[q].x + v[q].y * v[q].y
            + v[q].z * v[q].z + v[q].w * v[q].w;
    }
    #pragma unroll
    for (int o = 16; o > 0; o >>= 1) {
        s  += __shfl_xor_sync(0xffffffffu, s,  o);
        ss += __shfl_xor_sync(0xffffffffu, ss, o);
    }
    const float mu  = s * (1.0f / DIM);
    float var = (ss - (float)DIM * mu * mu) * (1.0f / (DIM - 1));
    var = fmaxf(var, 0.0f);
    const float inv = 1.0f / (sqrtf(var) + LN_EPS);

    const float4* gr = (const float4*)(G  + (size_t)g * DIM);
    const float4* br = (const float4*)(Bn + (size_t)g * DIM);
    uint2* dst = (uint2*)(g_ln + (size_t)r * DIM);
    #pragma unroll
    for (int q = 0; q < 8; q++) {
        const float4 gv = gr[lane + q * 32];
        const float4 bv = br[lane + q * 32];
        float2 y0, y1;
        y0.x = gv.x * (v[q].x - mu) * inv + bv.x;
        y0.y = gv.y * (v[q].y - mu) * inv + bv.y;
        y1.x = gv.z * (v[q].z - mu) * inv + bv.z;
        y1.y = gv.w * (v[q].w - mu) * inv + bv.w;
        __half2 h0 = __float22half2_rn(y0);
        __half2 h1 = __float22half2_rn(y1);
        uint2 o2;
        o2.x = *(const uint32_t*)&h0;
        o2.y = *(const uint32_t*)&h1;
        dst[lane + q * 32] = o2;
    }
}

// ---------------------------------------------------------------------------
// K1b (side stream): W2 transpose only.
// ---------------------------------------------------------------------------
__global__ __launch_bounds__(256)
void prep_w2_kernel(const float* __restrict__ W2) {
    __shared__ float tb[64][65];
    transpose_tile(W2, g_w2t, FFN, DIM, blockIdx.x, threadIdx.x, tb);
}

// ---------------------------------------------------------------------------
// K2/K3: fp16 mma.sync grouped GEMM, 128x128 tile, 256 threads, BK=64.
// row_base: starting token row of this launch's slice (SEQ-aligned).
// (Mainloop + epilogue identical to the round-13/15/16 best.)
// ---------------------------------------------------------------------------
template<bool RELU, bool RESID, bool OUT_HALF>
__global__ __launch_bounds__(256, 2)
void mma_gemm(const __half* __restrict__ A, const __half* __restrict__ Bt,
              const float* __restrict__ bias, const float* __restrict__ resid,
              void* __restrict__ Cv, int N, int K, int row_base) {
    extern __shared__ __half sm[];
    const int tid  = threadIdx.x;
    const int row0 = row_base + blockIdx.y * BM;
    const int col0 = blockIdx.x * BN;
    const int g    = g_dom[row0 >> 9];
    const __half* Bg = Bt + (size_t)g * N * K;

    const int lane  = tid & 31;
    const int wid   = tid >> 5;
    const int gid   = lane >> 2;
    const int tg    = lane & 3;
    const int warpm = wid & 1;
    const int warpn = wid >> 1;

    const uint32_t sm_base = smem_u32(sm);

    const uint32_t aoff_b =
        (uint32_t)((warpm * 64 + (lane & 7) + ((lane >> 3) & 1) * 8) * PADH
                   + (lane >> 4) * 8) * 2u;
    const uint32_t boff_b =
        (uint32_t)(BM * PADH) * 2u +
        (uint32_t)((warpn * 32 + (lane & 7) + (lane >> 4) * 8) * PADH
                   + ((lane >> 3) & 1) * 8) * 2u;

    auto load_stage = [&](int kt, int s) {
        const int k0 = kt * BKK;
        __half* As = sm + s * STAGE_H;
        __half* Bs = As + BM * PADH;
        #pragma unroll
        for (int j = 0; j < 4; j++) {
            int c = tid + j * 256;
            int m = c >> 3, kc = (c & 7) << 3;
            cp_async16(&As[m * PADH + kc],
                       A + (size_t)(row0 + m) * K + k0 + kc);
        }
        #pragma unroll
        for (int j = 0; j < 4; j++) {
            int c = tid + j * 256;
            int n = c >> 3, kc = (c & 7) << 3;
            cp_async16(&Bs[n * PADH + kc],
                       Bg + (size_t)(col0 + n) * K + k0 + kc);
        }
        CP_COMMIT();
    };

    auto frag_load = [&](uint32_t base, int ks, uint32_t a[4][4],
                         uint32_t b[4][2]) {
        const uint32_t Aaddr = base + aoff_b + (uint32_t)ks * 32u;
        const uint32_t Baddr = base + boff_b + (uint32_t)ks * 32u;
        #pragma unroll
        for (int mf = 0; mf < 4; mf++)
            ldsm_x4(a[mf][0], a[mf][1], a[mf][2], a[mf][3],
                    Aaddr + (uint32_t)(mf * 16 * PADH) * 2u);
        ldsm_x4(b[0][0], b[0][1], b[1][0], b[1][1], Baddr);
        ldsm_x4(b[2][0], b[2][1], b[3][0], b[3][1],
                Baddr + (uint32_t)(16 * PADH) * 2u);
    };

    float acc[4][4][4];
    #pragma unroll
    for (int i = 0; i < 4; i++)
        #pragma unroll
        for (int j = 0; j < 4; j++)
            #pragma unroll
            for (int q = 0; q < 4; q++) acc[i][j][q] = 0.f;

    const int KT = K / BKK;

    load_stage(0, 0);
    load_stage(1, 1);
    CP_WAIT(1);
    __syncthreads();

    uint32_t a[2][4][4], b[2][4][2];
    int s_cur = 0;
    int s_ld  = NSTG - 1;
    frag_load(sm_base, 0, a[0], b[0]);

    for (int kt = 0; kt < KT; kt++) {
        {
            int nx = kt + NSTG - 1;
            if (nx < KT) load_stage(nx, s_ld);
            else CP_COMMIT();
            if (++s_ld == NSTG) s_ld = 0;
        }
        const uint32_t base_cur = sm_base + (uint32_t)(s_cur * STAGE_H) * 2u;
        const int s_nxt = (s_cur + 1 == NSTG) ? 0 : s_cur + 1;
        const uint32_t base_nxt = sm_base + (uint32_t)(s_nxt * STAGE_H) * 2u;
        s_cur = s_nxt;

        #pragma unroll
        for (int ks = 0; ks < 3; ks++) {
            const int cb = ks & 1, nb = cb ^ 1;
            frag_load(base_cur, ks + 1, a[nb], b[nb]);
            #pragma unroll
            for (int mf = 0; mf < 4; mf++)
                #pragma unroll
                for (int nf = 0; nf < 4; nf++)
                    mma_f16(acc[mf][nf], a[cb][mf], b[cb][nf]);
        }

        if (kt + 1 < KT) {
            CP_WAIT(1);
            __syncthreads();
            frag_load(base_nxt, 0, a[0], b[0]);
        }

        #pragma unroll
        for (int mf = 0; mf < 4; mf++)
            #pragma unroll
            for (int nf = 0; nf < 4; nf++)
                mma_f16(acc[mf][nf], a[1][mf], b[1][nf]);
    }

    // epilogue (bias via float2)
    const float* biasg = bias + (size_t)g * N;
    #pragma unroll
    for (int mf = 0; mf < 4; mf++) {
        #pragma unroll
        for (int h = 0; h < 2; h++) {
            const int r = row0 + warpm * 64 + mf * 16 + gid + h * 8;
            const float* rrow = RESID ? (resid + (size_t)r * N) : nullptr;
            #pragma unroll
            for (int nf = 0; nf < 4; nf++) {
                const int cidx = col0 + warpn * 32 + nf * 8 + tg * 2;
                const float2 bb = *(const float2*)(biasg + cidx);
                float2 v;
                v.x = acc[mf][nf][h * 2 + 0] + bb.x;
                v.y = acc[mf][nf][h * 2 + 1] + bb.y;
                if (RELU) { v.x = fmaxf(v.x, 0.f); v.y = fmaxf(v.y, 0.f); }
                if (RESID) {
                    const float2 xv = *(const float2*)(rrow + cidx);
                    v.x += xv.x; v.y += xv.y;
                }
                if (OUT_HALF) {
                    __half2* crow = (__half2*)((__half*)Cv + (size_t)r * N + cidx);
                    *crow = __float22half2_rn(v);
                } else {
                    *(float2*)((float*)Cv + (size_t)r * N + cidx) = v;
                }
            }
        }
    }
}

// ---------------------------------------------------------------------------
extern "C" void kernel_launch(void* const* d_in, const int* in_sizes, int n_in,
                              void* d_out, int out_size) {
    const float* x   = (const float*)d_in[0];
    const int*   idx = (const int*)  d_in[1];
    const float* W1  = (const float*)d_in[2];
    const float* B1  = (const float*)d_in[3];
    const float* W2  = (const float*)d_in[4];
    const float* B2  = (const float*)d_in[5];
    const float* G   = (const float*)d_in[6];
    const float* Bn  = (const float*)d_in[7];
    float*       out = (float*)d_out;

    __half *ln_ptr, *h_ptr, *w1t_ptr, *w2t_ptr;
    cudaGetSymbolAddress((void**)&ln_ptr,  g_ln);
    cudaGetSymbolAddress((void**)&h_ptr,   g_h);
    cudaGetSymbolAddress((void**)&w1t_ptr, g_w1t);
    cudaGetSymbolAddress((void**)&w2t_ptr, g_w2t);

    // one-time setup (first call is the uncaptured correctness run)
    static cudaStream_t s_side = nullptr;
    static cudaEvent_t  ev_fork = nullptr, ev_w2 = nullptr,
                        ev_a = nullptr, ev_c = nullptr;
    static bool setup_done = false;
    if (!setup_done) {
        cudaFuncSetAttribute(mma_gemm<true, false, true>,
                             cudaFuncAttributeMaxDynamicSharedMemorySize, SMEM_BYTES);
        cudaFuncSetAttribute(mma_gemm<false, true, false>,
                             cudaFuncAttributeMaxDynamicSharedMemorySize, SMEM_BYTES);
        cudaStreamCreateWithFlags(&s_side, cudaStreamNonBlocking);
        cudaEventCreateWithFlags(&ev_fork, cudaEventDisableTiming);
        cudaEventCreateWithFlags(&ev_w2,   cudaEventDisableTiming);
        cudaEventCreateWithFlags(&ev_a,    cudaEventDisableTiming);
        cudaEventCreateWithFlags(&ev_c,    cudaEventDisableTiming);
        setup_done = true;
    }

    const dim3 g1_grid(FFN / BN, HALF_ROWS / BM);   // 16 x 64 per half
    const dim3 g2_grid(DIM / BN, HALF_ROWS / BM);   // 8 x 64 per half

    // main: dom -> fork
    dom_kernel<<<1, 32>>>(idx);
    cudaEventRecord(ev_fork, 0);

    // side: W2 transpose (needed only by gemm2)
    cudaStreamWaitEvent(s_side, ev_fork, 0);
    prep_w2_kernel<<<T_W2, 256, 0, s_side>>>(W2);
    cudaEventRecord(ev_w2, s_side);

    // main: W1 transpose + LN, then gemm1 first half
    prep_main_kernel<<<PREP_MAIN_GRID, 256>>>(W1, x, G, Bn);
    mma_gemm<true, false, true><<<g1_grid, 256, SMEM_BYTES>>>(
        ln_ptr, w1t_ptr, B1, nullptr, h_ptr, FFN, DIM, 0);
    cudaEventRecord(ev_a, 0);

    // main: gemm1 second half (overlaps side-stream gemm2 first half)
    mma_gemm<true, false, true><<<g1_grid, 256, SMEM_BYTES>>>(
        ln_ptr, w1t_ptr, B1, nullptr, h_ptr, FFN, DIM, HALF_ROWS);

    // side: gemm2 first half (after W2^T in-stream and gemm1 first half)
    cudaStreamWaitEvent(s_side, ev_a, 0);
    mma_gemm<false, true, false><<<g2_grid, 256, SMEM_BYTES, s_side>>>(
        h_ptr, w2t_ptr, B2, x, out, DIM, FFN, 0);
    cudaEventRecord(ev_c, s_side);

    // main: gemm2 second half (needs W2^T), then join side branch
    cudaStreamWaitEvent(0, ev_w2, 0);
    mma_gemm<false, true, false><<<g2_grid, 256, SMEM_BYTES>>>(
        h_ptr, w2t_ptr, B2, x, out, DIM, FFN, HALF_ROWS);
    cudaStreamWaitEvent(0, ev_c, 0);
}